// round 16
// baseline (speedup 1.0000x reference)
#include <cuda_runtime.h>
#include <cuda_bf16.h>
#include <cstdint>
#include <cstddef>

// Problem constants
#define E_    8
#define H_    2048
#define I_    2816
#define T_    512
#define TWO_I 5632
#define NB1   44   // (2I)/128 n-blocks for w13_scale
#define KB1   16   // H/128 k-blocks for w13_scale
#define NB2   16   // H/128 n-blocks for w2_scale
#define KB2   22   // I/128 k-blocks for w2_scale

// ---------------- device scratch (no runtime allocation allowed) -------------
__device__ float g_h[(size_t)E_ * T_ * TWO_I];   // GEMM1 output (fp32)
__device__ float g_act[(size_t)E_ * T_ * I_];    // SwiGLU output (fp32)
__device__ int   g_tok[E_ * T_];
__device__ float g_coef[E_ * T_];
__device__ int   g_cnt[E_];

// ---------------- shared tile: fp32 double-buffered stages + bf16 operands ---
struct Sm {
    float bf[2][128 * 64];          // B fp32 stage (weights), 32KB x2
    float af[2][64 * 64];           // A fp32 stage (gathered rows), 16KB x2
    __nv_bfloat16 ah[64 * 64];      // A hi (scale folded)
    __nv_bfloat16 al[64 * 64];      // A lo
    __nv_bfloat16 bb[128 * 64];     // B bf16 (exact convert)
};
#define SMEM_SZ ((int)sizeof(Sm))   // 131072 bytes

// ---------------- helpers ----------------------------------------------------
__device__ __forceinline__ unsigned pk2(float a, float b) {
    __nv_bfloat162 t = __floats2bfloat162_rn(a, b);  // a -> low, b -> high
    return *reinterpret_cast<unsigned*>(&t);
}
__device__ __forceinline__ unsigned pkh(__nv_bfloat16 a, __nv_bfloat16 b) {
    __nv_bfloat162 t; t.x = a; t.y = b;
    return *reinterpret_cast<unsigned*>(&t);
}

__device__ __forceinline__ void cpa16(void* dst, const void* src, bool pred) {
    unsigned d = (unsigned)__cvta_generic_to_shared(dst);
    int sz = pred ? 16 : 0;  // src-size 0 => full zero-fill
    asm volatile("cp.async.cg.shared.global [%0], [%1], 16, %2;\n"
                 :: "r"(d), "l"(src), "r"(sz));
}
#define CPA_COMMIT() asm volatile("cp.async.commit_group;\n")
#define CPA_WAIT1()  asm volatile("cp.async.wait_group 1;\n" ::: "memory")
#define CPA_WAIT0()  asm volatile("cp.async.wait_group 0;\n" ::: "memory")

__device__ __forceinline__ void ldsm4(unsigned& r0, unsigned& r1, unsigned& r2,
                                      unsigned& r3, const void* p) {
    unsigned a = (unsigned)__cvta_generic_to_shared(p);
    asm volatile("ldmatrix.sync.aligned.m8n8.x4.shared.b16 {%0,%1,%2,%3}, [%4];\n"
                 : "=r"(r0), "=r"(r1), "=r"(r2), "=r"(r3)
                 : "r"(a));
}

__device__ __forceinline__ void mma16816(float* c, unsigned a0, unsigned a1,
                                         unsigned a2, unsigned a3,
                                         unsigned b0, unsigned b1) {
    asm volatile(
        "mma.sync.aligned.m16n8k16.row.col.f32.bf16.bf16.f32 "
        "{%0,%1,%2,%3}, {%4,%5,%6,%7}, {%8,%9}, {%0,%1,%2,%3};\n"
        : "+f"(c[0]), "+f"(c[1]), "+f"(c[2]), "+f"(c[3])
        : "r"(a0), "r"(a1), "r"(a2), "r"(a3), "r"(b0), "r"(b1));
}

// bf16 buffers: rows are 64 bf16 (128B) wide; 8 chunks of 8 bf16 (16B).
// chunk' = chunk ^ (row&7) -> conflict-free ldmatrix across 8 rows. (verified)
__device__ __forceinline__ int swz(int row, int chunk) {
    return row * 64 + ((chunk ^ (row & 7)) << 3);
}

// ---------------- stage issue / convert --------------------------------------
// A stage: 64 rows x 64 fp32 (256B/row = 16 chunks of 16B). thread t: row=t>>2,
// chunks (t&3)*4 .. +3.
__device__ __forceinline__ void issueA(Sm& sm, int st, const float* arow,
                                       bool av, int k0, int ar, int aq) {
#pragma unroll
    for (int cc = 0; cc < 4; ++cc) {
        int c = aq * 4 + cc;
        cpa16(&sm.af[st][ar * 64 + c * 4], arow + k0 + c * 4, av);
    }
}
// B stage: 128 rows x 64 fp32. thread t: row=t>>1, chunks (t&1)*8 .. +7.
__device__ __forceinline__ void issueB(Sm& sm, int st, const float* brow,
                                       int k0, int br, int bh) {
#pragma unroll
    for (int cc = 0; cc < 8; ++cc) {
        int c = bh * 8 + cc;
        cpa16(&sm.bf[st][br * 64 + c * 4], brow + k0 + c * 4, true);
    }
}

// Convert A: p = scale * x (fp32), split into bf16 hi/lo, store swizzled.
__device__ __forceinline__ void convA(Sm& sm, int cur, float sc, int ar, int aq) {
#pragma unroll
    for (int cc = 0; cc < 2; ++cc) {
        int bc = aq * 2 + cc;  // bf16 chunk (8 bf16 = 8 fp32 source)
        const float* p = &sm.af[cur][ar * 64 + bc * 8];
        float4 f0 = *(const float4*)p;
        float4 f1 = *(const float4*)(p + 4);
        float q0 = f0.x * sc, q1 = f0.y * sc, q2 = f0.z * sc, q3 = f0.w * sc;
        float q4 = f1.x * sc, q5 = f1.y * sc, q6 = f1.z * sc, q7 = f1.w * sc;
        __nv_bfloat16 h0 = __float2bfloat16(q0), h1 = __float2bfloat16(q1);
        __nv_bfloat16 h2 = __float2bfloat16(q2), h3 = __float2bfloat16(q3);
        __nv_bfloat16 h4 = __float2bfloat16(q4), h5 = __float2bfloat16(q5);
        __nv_bfloat16 h6 = __float2bfloat16(q6), h7 = __float2bfloat16(q7);
        uint4 uh, ul;
        uh.x = pkh(h0, h1); uh.y = pkh(h2, h3);
        uh.z = pkh(h4, h5); uh.w = pkh(h6, h7);
        ul.x = pk2(q0 - __bfloat162float(h0), q1 - __bfloat162float(h1));
        ul.y = pk2(q2 - __bfloat162float(h2), q3 - __bfloat162float(h3));
        ul.z = pk2(q4 - __bfloat162float(h4), q5 - __bfloat162float(h5));
        ul.w = pk2(q6 - __bfloat162float(h6), q7 - __bfloat162float(h7));
        *(uint4*)(sm.ah + swz(ar, bc)) = uh;
        *(uint4*)(sm.al + swz(ar, bc)) = ul;
    }
}

// Convert B: exact fp32 -> bf16 (weights are fp8-representable).
__device__ __forceinline__ void convB(Sm& sm, int cur, int br, int bh) {
#pragma unroll
    for (int cc = 0; cc < 4; ++cc) {
        int bc = bh * 4 + cc;
        const float* p = &sm.bf[cur][br * 64 + bc * 8];
        float4 f0 = *(const float4*)p;
        float4 f1 = *(const float4*)(p + 4);
        uint4 u;
        u.x = pk2(f0.x, f0.y); u.y = pk2(f0.z, f0.w);
        u.z = pk2(f1.x, f1.y); u.w = pk2(f1.z, f1.w);
        *(uint4*)(sm.bb + swz(br, bc)) = u;
    }
}

// ---------------- zero output -------------------------------------------------
__global__ void k_zero(float* __restrict__ out) {
    out[blockIdx.x * 256 + threadIdx.x] = 0.f;
}

// ---------------- routing: per-expert token list + coef ----------------------
// topk_ids may be int64 or int32 depending on jax x64 config; detect at runtime.
__global__ void k_route(const void* __restrict__ ids_raw,
                        const float* __restrict__ w) {
    __shared__ int s64;
    int tid = threadIdx.x;
    if (tid == 0) s64 = 1;
    __syncthreads();
    const long long* p64 = (const long long*)ids_raw;
    const int*       p32 = (const int*)ids_raw;
    for (int i = tid; i < 512; i += 256) {
        long long v = p64[i];
        if (v < 0 || v >= E_) s64 = 0;
    }
    __syncthreads();
    int is64 = s64;

    int warp = tid >> 5, lane = tid & 31;
    int e = warp;
    int c = 0;
    for (int t0 = 0; t0 < T_; t0 += 32) {
        int t = t0 + lane;
        int id0, id1;
        if (is64) { id0 = (int)p64[2 * t]; id1 = (int)p64[2 * t + 1]; }
        else      { id0 = p32[2 * t];      id1 = p32[2 * t + 1]; }
        float cf = 0.f;
        bool hit = false;
        if (id0 == e) { cf += w[2 * t];     hit = true; }
        if (id1 == e) { cf += w[2 * t + 1]; hit = true; }
        unsigned m = __ballot_sync(0xffffffffu, hit);
        if (hit) {
            int pos = c + __popc(m & ((1u << lane) - 1u));
            g_tok[e * T_ + pos]  = t;
            g_coef[e * T_ + pos] = cf;
        }
        c += __popc(m);
    }
    if (lane == 0) g_cnt[e] = c;
}

// ---------------- GEMM1: g_h[slot,n] = sum_k (s*x)[tok,k] * W13[e,n,k] -------
__global__ __launch_bounds__(256, 1)
void k_gemm1(const float* __restrict__ x, const float* __restrict__ w13,
             const float* __restrict__ w13s) {
    int nt = blockIdx.x, mt = blockIdx.y, e = blockIdx.z;
    int cnt = g_cnt[e];
    if (mt * 64 >= cnt) return;
    extern __shared__ char smraw[];
    Sm& sm = *reinterpret_cast<Sm*>(smraw);

    int tid = threadIdx.x, lane = tid & 31, warp = tid >> 5;
    int wm = warp >> 1, wn = warp & 1;
    int ar = tid >> 2, aq = tid & 3;
    int br = tid >> 1, bh = tid & 1;

    int mrow = mt * 64 + ar;
    bool av = mrow < cnt;
    const float* arow = x + (size_t)(av ? g_tok[e * T_ + mrow] : 0) * H_;
    const float* brow = w13 + ((size_t)e * TWO_I + (size_t)nt * 128 + br) * H_;
    const float* scp  = w13s + ((size_t)e * NB1 + nt) * KB1;

    float acc[8][4];
#pragma unroll
    for (int s = 0; s < 8; ++s)
#pragma unroll
        for (int j = 0; j < 4; ++j) acc[s][j] = 0.f;

    issueA(sm, 0, arow, av, 0, ar, aq);
    issueB(sm, 0, brow, 0, br, bh);
    CPA_COMMIT();

    const int NC = H_ / 64;  // 32
    for (int kc = 0; kc < NC; ++kc) {
        int cur = kc & 1;
        if (kc + 1 < NC) {
            issueA(sm, cur ^ 1, arow, av, (kc + 1) * 64, ar, aq);
            issueB(sm, cur ^ 1, brow, (kc + 1) * 64, br, bh);
            CPA_COMMIT();
            CPA_WAIT1();
        } else {
            CPA_WAIT0();
        }
        __syncthreads();
        convA(sm, cur, scp[kc >> 1], ar, aq);
        convB(sm, cur, br, bh);
        __syncthreads();

#pragma unroll
        for (int ks = 0; ks < 4; ++ks) {
            unsigned ah0, ah1, ah2, ah3, al0, al1, al2, al3;
            {
                int row = wm * 16 + (lane & 15);
                int chunk = ks * 2 + (lane >> 4);
                ldsm4(ah0, ah1, ah2, ah3, sm.ah + swz(row, chunk));
                ldsm4(al0, al1, al2, al3, sm.al + swz(row, chunk));
            }
            unsigned bq[16];
#pragma unroll
            for (int g = 0; g < 4; ++g) {
                int row = wn * 64 + g * 16 + (lane & 7) + ((lane >> 4) << 3);
                int chunk = ks * 2 + ((lane >> 3) & 1);
                ldsm4(bq[4 * g], bq[4 * g + 1], bq[4 * g + 2], bq[4 * g + 3],
                      sm.bb + swz(row, chunk));
            }
#pragma unroll
            for (int s = 0; s < 8; ++s) {
                unsigned b0 = bq[4 * (s >> 1) + 2 * (s & 1)];
                unsigned b1 = bq[4 * (s >> 1) + 2 * (s & 1) + 1];
                mma16816(acc[s], ah0, ah1, ah2, ah3, b0, b1);
                mma16816(acc[s], al0, al1, al2, al3, b0, b1);
            }
        }
    }

    // epilogue: write fp32 h tile
    int r0 = lane >> 2, cb = (lane & 3) * 2;
    size_t rowbase = (size_t)(e * T_ + mt * 64 + wm * 16 + r0) * TWO_I;
    int colbase = nt * 128 + wn * 64 + cb;
#pragma unroll
    for (int s = 0; s < 8; ++s) {
        float* p0 = g_h + rowbase + colbase + s * 8;
        *(float2*)p0 = make_float2(acc[s][0], acc[s][1]);
        *(float2*)(p0 + (size_t)8 * TWO_I) = make_float2(acc[s][2], acc[s][3]);
    }
}

// ---------------- SwiGLU (fp32 in, fp32 out) ----------------------------------
__global__ void k_act() {
    int ic = blockIdx.x, mt = blockIdx.y, e = blockIdx.z;
    if (mt * 64 >= g_cnt[e]) return;
    int tid = threadIdx.x;
    int c4 = (tid & 31) * 4;  // 0..124
    int r0 = tid >> 5;        // 0..7
#pragma unroll
    for (int rr = 0; rr < 64; rr += 8) {
        int row = mt * 64 + rr + r0;
        size_t hbase = (size_t)(e * T_ + row) * TWO_I + (size_t)ic * 128 + c4;
        float4 g = *(const float4*)(g_h + hbase);
        float4 u = *(const float4*)(g_h + hbase + I_);
        float4 a;
        a.x = u.x * (g.x / (1.f + __expf(-g.x)));
        a.y = u.y * (g.y / (1.f + __expf(-g.y)));
        a.z = u.z * (g.z / (1.f + __expf(-g.z)));
        a.w = u.w * (g.w / (1.f + __expf(-g.w)));
        *(float4*)(g_act + (size_t)(e * T_ + row) * I_ + (size_t)ic * 128 + c4) = a;
    }
}

// ---------------- GEMM2: out[tok] += coef * (s*act) @ W2^T --------------------
__global__ __launch_bounds__(256, 1)
void k_gemm2(const float* __restrict__ w2, const float* __restrict__ w2s,
             float* __restrict__ out) {
    int nt = blockIdx.x, mt = blockIdx.y, e = blockIdx.z;
    int cnt = g_cnt[e];
    if (mt * 64 >= cnt) return;
    extern __shared__ char smraw[];
    Sm& sm = *reinterpret_cast<Sm*>(smraw);

    int tid = threadIdx.x, lane = tid & 31, warp = tid >> 5;
    int wm = warp >> 1, wn = warp & 1;
    int ar = tid >> 2, aq = tid & 3;
    int br = tid >> 1, bh = tid & 1;

    int mrow = mt * 64 + ar;
    bool av = mrow < cnt;
    const float* arow = g_act + (size_t)(e * T_ + mrow) * I_;
    const float* brow = w2 + ((size_t)e * H_ + (size_t)nt * 128 + br) * I_;
    const float* scp  = w2s + ((size_t)e * NB2 + nt) * KB2;

    float acc[8][4];
#pragma unroll
    for (int s = 0; s < 8; ++s)
#pragma unroll
        for (int j = 0; j < 4; ++j) acc[s][j] = 0.f;

    issueA(sm, 0, arow, av, 0, ar, aq);
    issueB(sm, 0, brow, 0, br, bh);
    CPA_COMMIT();

    const int NC = I_ / 64;  // 44
    for (int kc = 0; kc < NC; ++kc) {
        int cur = kc & 1;
        if (kc + 1 < NC) {
            issueA(sm, cur ^ 1, arow, av, (kc + 1) * 64, ar, aq);
            issueB(sm, cur ^ 1, brow, (kc + 1) * 64, br, bh);
            CPA_COMMIT();
            CPA_WAIT1();
        } else {
            CPA_WAIT0();
        }
        __syncthreads();
        convA(sm, cur, scp[kc >> 1], ar, aq);
        convB(sm, cur, br, bh);
        __syncthreads();

#pragma unroll
        for (int ks = 0; ks < 4; ++ks) {
            unsigned ah0, ah1, ah2, ah3, al0, al1, al2, al3;
            {
                int row = wm * 16 + (lane & 15);
                int chunk = ks * 2 + (lane >> 4);
                ldsm4(ah0, ah1, ah2, ah3, sm.ah + swz(row, chunk));
                ldsm4(al0, al1, al2, al3, sm.al + swz(row, chunk));
            }
            unsigned bq[16];
#pragma unroll
            for (int g = 0; g < 4; ++g) {
                int row = wn * 64 + g * 16 + (lane & 7) + ((lane >> 4) << 3);
                int chunk = ks * 2 + ((lane >> 3) & 1);
                ldsm4(bq[4 * g], bq[4 * g + 1], bq[4 * g + 2], bq[4 * g + 3],
                      sm.bb + swz(row, chunk));
            }
#pragma unroll
            for (int s = 0; s < 8; ++s) {
                unsigned b0 = bq[4 * (s >> 1) + 2 * (s & 1)];
                unsigned b1 = bq[4 * (s >> 1) + 2 * (s & 1) + 1];
                mma16816(acc[s], ah0, ah1, ah2, ah3, b0, b1);
                mma16816(acc[s], al0, al1, al2, al3, b0, b1);
            }
        }
    }

    // epilogue: weighted scatter-add (<=2 adds/element -> deterministic)
    int r0 = lane >> 2, cb = (lane & 3) * 2;
    int rloc0 = mt * 64 + wm * 16 + r0;
#pragma unroll
    for (int hrow = 0; hrow < 2; ++hrow) {
        int rl = rloc0 + hrow * 8;
        if (rl < cnt) {
            float cf = g_coef[e * T_ + rl];
            if (cf != 0.f) {
                int tok = g_tok[e * T_ + rl];
                float* op = out + (size_t)tok * H_ + nt * 128 + wn * 64 + cb;
#pragma unroll
                for (int s = 0; s < 8; ++s) {
                    atomicAdd(op + s * 8,     cf * acc[s][2 * hrow + 0]);
                    atomicAdd(op + s * 8 + 1, cf * acc[s][2 * hrow + 1]);
                }
            }
        }
    }
}

// ---------------- launcher ---------------------------------------------------
extern "C" void kernel_launch(void* const* d_in, const int* in_sizes, int n_in,
                              void* d_out, int out_size) {
    const float* x    = (const float*)d_in[0];
    const void*  ids  = d_in[1];
    const float* tw   = (const float*)d_in[2];
    const float* w13  = (const float*)d_in[3];
    const float* w13s = (const float*)d_in[4];
    const float* w2   = (const float*)d_in[5];
    const float* w2s  = (const float*)d_in[6];
    float* out = (float*)d_out;

    cudaFuncSetAttribute(k_gemm1, cudaFuncAttributeMaxDynamicSharedMemorySize,
                         SMEM_SZ);
    cudaFuncSetAttribute(k_gemm2, cudaFuncAttributeMaxDynamicSharedMemorySize,
                         SMEM_SZ);

    k_zero<<<(T_ * H_) / 256, 256>>>(out);
    k_route<<<1, 256>>>(ids, tw);
    dim3 g1(NB1, 8, E_);
    k_gemm1<<<g1, 256, SMEM_SZ>>>(x, w13, w13s);
    dim3 ga(KB2, 8, E_);
    k_act<<<ga, 256>>>();
    dim3 g2(NB2, 8, E_);
    k_gemm2<<<g2, 256, SMEM_SZ>>>(w2, w2s, out);
}

// round 17
// speedup vs baseline: 2.1446x; 2.1446x over previous
#include <cuda_runtime.h>
#include <cuda_bf16.h>
#include <cstdint>
#include <cstddef>

// Problem constants
#define E_    8
#define H_    2048
#define I_    2816
#define T_    512
#define TWO_I 5632
#define NB1   44   // (2I)/128 n-blocks for w13_scale
#define KB1   16   // H/128 k-blocks for w13_scale
#define NB2   16   // H/128 n-blocks for w2_scale
#define KB2   22   // I/128 k-blocks for w2_scale

// ---------------- device scratch (no runtime allocation allowed) -------------
__device__ float g_h[(size_t)E_ * T_ * TWO_I];   // GEMM1 output (fp32)
__device__ float g_act[(size_t)E_ * T_ * I_];    // SwiGLU output (fp32)
__device__ int   g_tok[E_ * T_];
__device__ float g_coef[E_ * T_];
__device__ int   g_cnt[E_];

// ---------------- shared tile: bf16 operands, double-buffered ----------------
// Tiles are 128 rows x 32 bf16 (64B rows). 48KB total.
struct Sm {
    __nv_bfloat16 ah[2][128 * 32];  // A hi (scale folded)
    __nv_bfloat16 al[2][128 * 32];  // A lo
    __nv_bfloat16 bb[2][128 * 32];  // B (exact bf16)
};
#define SMEM_SZ ((int)sizeof(Sm))   // 49152 bytes

// ---------------- helpers ----------------------------------------------------
__device__ __forceinline__ unsigned pk2(float a, float b) {
    __nv_bfloat162 t = __floats2bfloat162_rn(a, b);  // a -> low, b -> high
    return *reinterpret_cast<unsigned*>(&t);
}
__device__ __forceinline__ unsigned pkh(__nv_bfloat16 a, __nv_bfloat16 b) {
    __nv_bfloat162 t; t.x = a; t.y = b;
    return *reinterpret_cast<unsigned*>(&t);
}

__device__ __forceinline__ void ldsm4(unsigned& r0, unsigned& r1, unsigned& r2,
                                      unsigned& r3, const void* p) {
    unsigned a = (unsigned)__cvta_generic_to_shared(p);
    asm volatile("ldmatrix.sync.aligned.m8n8.x4.shared.b16 {%0,%1,%2,%3}, [%4];\n"
                 : "=r"(r0), "=r"(r1), "=r"(r2), "=r"(r3)
                 : "r"(a));
}

__device__ __forceinline__ void mma16816(float* c, unsigned a0, unsigned a1,
                                         unsigned a2, unsigned a3,
                                         unsigned b0, unsigned b1) {
    asm volatile(
        "mma.sync.aligned.m16n8k16.row.col.f32.bf16.bf16.f32 "
        "{%0,%1,%2,%3}, {%4,%5,%6,%7}, {%8,%9}, {%0,%1,%2,%3};\n"
        : "+f"(c[0]), "+f"(c[1]), "+f"(c[2]), "+f"(c[3])
        : "r"(a0), "r"(a1), "r"(a2), "r"(a3), "r"(b0), "r"(b1));
}

// bf16 tile: rows of 32 bf16 (64B) = 4 chunks of 16B.
// chunk' = chunk ^ ((row>>1)&3): conflict-free for ldmatrix 8-lane phases
// (even rows hit banks 0-15 with 4 distinct quads, odd rows 16-31 likewise).
__device__ __forceinline__ int offb(int row, int chunk) {
    return row * 32 + ((chunk ^ ((row >> 1) & 3)) << 3);
}

// ---------------- register staging loads -------------------------------------
__device__ __forceinline__ void ld16(float4* r, const float* p, bool pred) {
#pragma unroll
    for (int i = 0; i < 4; ++i)
        r[i] = pred ? *(const float4*)(p + i * 4) : make_float4(0.f, 0.f, 0.f, 0.f);
}

// Convert + store A: p = sc*x in fp32, split hi/lo bf16. Thread owns row lr,
// 16 values at bf16 chunks lh*2, lh*2+1.
__device__ __forceinline__ void storeA(__nv_bfloat16* ah, __nv_bfloat16* al,
                                       const float4* ra, float sc, int lr, int lh) {
#pragma unroll
    for (int half = 0; half < 2; ++half) {
        float4 f0 = ra[half * 2], f1 = ra[half * 2 + 1];
        float q0 = f0.x * sc, q1 = f0.y * sc, q2 = f0.z * sc, q3 = f0.w * sc;
        float q4 = f1.x * sc, q5 = f1.y * sc, q6 = f1.z * sc, q7 = f1.w * sc;
        __nv_bfloat16 h0 = __float2bfloat16(q0), h1 = __float2bfloat16(q1);
        __nv_bfloat16 h2 = __float2bfloat16(q2), h3 = __float2bfloat16(q3);
        __nv_bfloat16 h4 = __float2bfloat16(q4), h5 = __float2bfloat16(q5);
        __nv_bfloat16 h6 = __float2bfloat16(q6), h7 = __float2bfloat16(q7);
        uint4 uh, ul;
        uh.x = pkh(h0, h1); uh.y = pkh(h2, h3);
        uh.z = pkh(h4, h5); uh.w = pkh(h6, h7);
        ul.x = pk2(q0 - __bfloat162float(h0), q1 - __bfloat162float(h1));
        ul.y = pk2(q2 - __bfloat162float(h2), q3 - __bfloat162float(h3));
        ul.z = pk2(q4 - __bfloat162float(h4), q5 - __bfloat162float(h5));
        ul.w = pk2(q6 - __bfloat162float(h6), q7 - __bfloat162float(h7));
        int c = lh * 2 + half;
        *(uint4*)(ah + offb(lr, c)) = uh;
        *(uint4*)(al + offb(lr, c)) = ul;
    }
}

// Convert + store B: exact fp32 -> bf16 (weights fp8-representable).
__device__ __forceinline__ void storeB(__nv_bfloat16* bb, const float4* rb,
                                       int lr, int lh) {
#pragma unroll
    for (int half = 0; half < 2; ++half) {
        float4 f0 = rb[half * 2], f1 = rb[half * 2 + 1];
        uint4 u;
        u.x = pk2(f0.x, f0.y); u.y = pk2(f0.z, f0.w);
        u.z = pk2(f1.x, f1.y); u.w = pk2(f1.z, f1.w);
        *(uint4*)(bb + offb(lr, lh * 2 + half)) = u;
    }
}

// ---------------- mma phase over one bf16 stage (KC=32) ----------------------
__device__ __forceinline__ void mma_phase(const __nv_bfloat16* ah,
                                          const __nv_bfloat16* al,
                                          const __nv_bfloat16* bb,
                                          float acc[2][8][4],
                                          int wm, int wn, int lane) {
#pragma unroll
    for (int ks = 0; ks < 2; ++ks) {
        unsigned AH[2][4], AL[2][4];
#pragma unroll
        for (int mf = 0; mf < 2; ++mf) {
            int row = wm * 32 + mf * 16 + (lane & 15);
            int c = ks * 2 + (lane >> 4);
            ldsm4(AH[mf][0], AH[mf][1], AH[mf][2], AH[mf][3], ah + offb(row, c));
            ldsm4(AL[mf][0], AL[mf][1], AL[mf][2], AL[mf][3], al + offb(row, c));
        }
        unsigned bq[16];
#pragma unroll
        for (int g = 0; g < 4; ++g) {
            int row = wn * 64 + g * 16 + (lane & 7) + ((lane >> 4) << 3);
            int c = ks * 2 + ((lane >> 3) & 1);
            ldsm4(bq[4 * g], bq[4 * g + 1], bq[4 * g + 2], bq[4 * g + 3],
                  bb + offb(row, c));
        }
        // hi pass then lo pass: RAW distance 8 on each accumulator
#pragma unroll
        for (int s = 0; s < 8; ++s) {
            unsigned b0 = bq[4 * (s >> 1) + 2 * (s & 1)];
            unsigned b1 = bq[4 * (s >> 1) + 2 * (s & 1) + 1];
#pragma unroll
            for (int mf = 0; mf < 2; ++mf)
                mma16816(acc[mf][s], AH[mf][0], AH[mf][1], AH[mf][2], AH[mf][3],
                         b0, b1);
        }
#pragma unroll
        for (int s = 0; s < 8; ++s) {
            unsigned b0 = bq[4 * (s >> 1) + 2 * (s & 1)];
            unsigned b1 = bq[4 * (s >> 1) + 2 * (s & 1) + 1];
#pragma unroll
            for (int mf = 0; mf < 2; ++mf)
                mma16816(acc[mf][s], AL[mf][0], AL[mf][1], AL[mf][2], AL[mf][3],
                         b0, b1);
        }
    }
}

// ---------------- zero output -------------------------------------------------
__global__ void k_zero(float* __restrict__ out) {
    out[blockIdx.x * 256 + threadIdx.x] = 0.f;
}

// ---------------- routing: per-expert token list + coef ----------------------
// topk_ids may be int64 or int32 depending on jax x64 config; detect at runtime.
__global__ void k_route(const void* __restrict__ ids_raw,
                        const float* __restrict__ w) {
    __shared__ int s64;
    int tid = threadIdx.x;
    if (tid == 0) s64 = 1;
    __syncthreads();
    const long long* p64 = (const long long*)ids_raw;
    const int*       p32 = (const int*)ids_raw;
    for (int i = tid; i < 512; i += 256) {
        long long v = p64[i];
        if (v < 0 || v >= E_) s64 = 0;
    }
    __syncthreads();
    int is64 = s64;

    int warp = tid >> 5, lane = tid & 31;
    int e = warp;
    int c = 0;
    for (int t0 = 0; t0 < T_; t0 += 32) {
        int t = t0 + lane;
        int id0, id1;
        if (is64) { id0 = (int)p64[2 * t]; id1 = (int)p64[2 * t + 1]; }
        else      { id0 = p32[2 * t];      id1 = p32[2 * t + 1]; }
        float cf = 0.f;
        bool hit = false;
        if (id0 == e) { cf += w[2 * t];     hit = true; }
        if (id1 == e) { cf += w[2 * t + 1]; hit = true; }
        unsigned m = __ballot_sync(0xffffffffu, hit);
        if (hit) {
            int pos = c + __popc(m & ((1u << lane) - 1u));
            g_tok[e * T_ + pos]  = t;
            g_coef[e * T_ + pos] = cf;
        }
        c += __popc(m);
    }
    if (lane == 0) g_cnt[e] = c;
}

// ---------------- GEMM1: g_h[slot,n] = sum_k (s*x)[tok,k] * W13[e,n,k] -------
// BM=128, BN=128, KC=32; 8 warps (4m x 2n), warp tile 32x64.
__global__ __launch_bounds__(256, 1)
void k_gemm1(const float* __restrict__ x, const float* __restrict__ w13,
             const float* __restrict__ w13s) {
    int nt = blockIdx.x, mt = blockIdx.y, e = blockIdx.z;
    int cnt = g_cnt[e];
    if (mt * 128 >= cnt) return;
    extern __shared__ char smraw[];
    Sm& sm = *reinterpret_cast<Sm*>(smraw);

    int t = threadIdx.x, lane = t & 31, warp = t >> 5;
    int wm = warp >> 1, wn = warp & 1;
    int lr = t >> 1, lh = t & 1;

    int slot = mt * 128 + lr;
    bool av = slot < cnt;
    const float* arow =
        x + (size_t)(av ? g_tok[e * T_ + slot] : 0) * H_ + lh * 16;
    const float* brow =
        w13 + ((size_t)e * TWO_I + (size_t)nt * 128 + lr) * H_ + lh * 16;
    const float* scp = w13s + ((size_t)e * NB1 + nt) * KB1;

    float acc[2][8][4];
#pragma unroll
    for (int mf = 0; mf < 2; ++mf)
#pragma unroll
        for (int s = 0; s < 8; ++s)
#pragma unroll
            for (int j = 0; j < 4; ++j) acc[mf][s][j] = 0.f;

    float4 ra[4], rb[4];
    ld16(ra, arow, av);
    ld16(rb, brow, true);

    const int NC = H_ / 32;  // 64
    for (int kc = 0; kc < NC; ++kc) {
        int cur = kc & 1;
        storeA(sm.ah[cur], sm.al[cur], ra, scp[kc >> 2], lr, lh);
        storeB(sm.bb[cur], rb, lr, lh);
        __syncthreads();
        if (kc + 1 < NC) {
            ld16(ra, arow + (kc + 1) * 32, av);
            ld16(rb, brow + (kc + 1) * 32, true);
        }
        mma_phase(sm.ah[cur], sm.al[cur], sm.bb[cur], acc, wm, wn, lane);
        __syncthreads();
    }

    // epilogue: write fp32 h tile (invalid rows carry zeros -> harmless)
    int r0 = lane >> 2, cb = (lane & 3) * 2;
#pragma unroll
    for (int mf = 0; mf < 2; ++mf) {
        size_t row0 = (size_t)(e * T_ + mt * 128 + wm * 32 + mf * 16 + r0);
#pragma unroll
        for (int s = 0; s < 8; ++s) {
            int col = nt * 128 + wn * 64 + s * 8 + cb;
            *(float2*)&g_h[row0 * TWO_I + col] =
                make_float2(acc[mf][s][0], acc[mf][s][1]);
            *(float2*)&g_h[(row0 + 8) * TWO_I + col] =
                make_float2(acc[mf][s][2], acc[mf][s][3]);
        }
    }
}

// ---------------- SwiGLU (fp32 in, fp32 out) ----------------------------------
__global__ void k_act() {
    int ic = blockIdx.x, mt = blockIdx.y, e = blockIdx.z;
    if (mt * 64 >= g_cnt[e]) return;
    int tid = threadIdx.x;
    int c4 = (tid & 31) * 4;
    int r0 = tid >> 5;
#pragma unroll
    for (int rr = 0; rr < 64; rr += 8) {
        int row = mt * 64 + rr + r0;
        size_t hbase = (size_t)(e * T_ + row) * TWO_I + (size_t)ic * 128 + c4;
        float4 g = *(const float4*)(g_h + hbase);
        float4 u = *(const float4*)(g_h + hbase + I_);
        float4 a;
        a.x = u.x * (g.x / (1.f + __expf(-g.x)));
        a.y = u.y * (g.y / (1.f + __expf(-g.y)));
        a.z = u.z * (g.z / (1.f + __expf(-g.z)));
        a.w = u.w * (g.w / (1.f + __expf(-g.w)));
        *(float4*)(g_act + (size_t)(e * T_ + row) * I_ + (size_t)ic * 128 + c4) = a;
    }
}

// ---------------- GEMM2: out[tok] += coef * (s*act) @ W2^T --------------------
__global__ __launch_bounds__(256, 1)
void k_gemm2(const float* __restrict__ w2, const float* __restrict__ w2s,
             float* __restrict__ out) {
    int nt = blockIdx.x, mt = blockIdx.y, e = blockIdx.z;
    int cnt = g_cnt[e];
    if (mt * 128 >= cnt) return;
    extern __shared__ char smraw[];
    Sm& sm = *reinterpret_cast<Sm*>(smraw);

    int t = threadIdx.x, lane = t & 31, warp = t >> 5;
    int wm = warp >> 1, wn = warp & 1;
    int lr = t >> 1, lh = t & 1;

    int slot = mt * 128 + lr;
    bool av = slot < cnt;
    const float* arow = g_act + (size_t)(e * T_ + slot) * I_ + lh * 16;
    const float* brow =
        w2 + ((size_t)e * H_ + (size_t)nt * 128 + lr) * I_ + lh * 16;
    const float* scp = w2s + ((size_t)e * NB2 + nt) * KB2;

    float acc[2][8][4];
#pragma unroll
    for (int mf = 0; mf < 2; ++mf)
#pragma unroll
        for (int s = 0; s < 8; ++s)
#pragma unroll
            for (int j = 0; j < 4; ++j) acc[mf][s][j] = 0.f;

    float4 ra[4], rb[4];
    ld16(ra, arow, av);
    ld16(rb, brow, true);

    const int NC = I_ / 32;  // 88
    for (int kc = 0; kc < NC; ++kc) {
        int cur = kc & 1;
        storeA(sm.ah[cur], sm.al[cur], ra, scp[kc >> 2], lr, lh);
        storeB(sm.bb[cur], rb, lr, lh);
        __syncthreads();
        if (kc + 1 < NC) {
            ld16(ra, arow + (kc + 1) * 32, av);
            ld16(rb, brow + (kc + 1) * 32, true);
        }
        mma_phase(sm.ah[cur], sm.al[cur], sm.bb[cur], acc, wm, wn, lane);
        __syncthreads();
    }

    // epilogue: weighted scatter-add (<=2 adds/element -> deterministic)
    int r0 = lane >> 2, cb = (lane & 3) * 2;
#pragma unroll
    for (int mf = 0; mf < 2; ++mf) {
#pragma unroll
        for (int hrow = 0; hrow < 2; ++hrow) {
            int rl = mt * 128 + wm * 32 + mf * 16 + r0 + hrow * 8;
            if (rl < cnt) {
                float cf = g_coef[e * T_ + rl];
                if (cf != 0.f) {
                    int tok = g_tok[e * T_ + rl];
                    float* op = out + (size_t)tok * H_ + nt * 128 + wn * 64 + cb;
#pragma unroll
                    for (int s = 0; s < 8; ++s) {
                        atomicAdd(op + s * 8,     cf * acc[mf][s][2 * hrow + 0]);
                        atomicAdd(op + s * 8 + 1, cf * acc[mf][s][2 * hrow + 1]);
                    }
                }
            }
        }
    }
}

// ---------------- launcher ---------------------------------------------------
extern "C" void kernel_launch(void* const* d_in, const int* in_sizes, int n_in,
                              void* d_out, int out_size) {
    const float* x    = (const float*)d_in[0];
    const void*  ids  = d_in[1];
    const float* tw   = (const float*)d_in[2];
    const float* w13  = (const float*)d_in[3];
    const float* w13s = (const float*)d_in[4];
    const float* w2   = (const float*)d_in[5];
    const float* w2s  = (const float*)d_in[6];
    float* out = (float*)d_out;

    cudaFuncSetAttribute(k_gemm1, cudaFuncAttributeMaxDynamicSharedMemorySize,
                         SMEM_SZ);
    cudaFuncSetAttribute(k_gemm2, cudaFuncAttributeMaxDynamicSharedMemorySize,
                         SMEM_SZ);

    k_zero<<<(T_ * H_) / 256, 256>>>(out);
    k_route<<<1, 256>>>(ids, tw);
    dim3 g1(NB1, T_ / 128, E_);
    k_gemm1<<<g1, 256, SMEM_SZ>>>(x, w13, w13s);
    dim3 ga(KB2, T_ / 64, E_);
    k_act<<<ga, 256>>>();
    dim3 g2(NB2, T_ / 128, E_);
    k_gemm2<<<g2, 256, SMEM_SZ>>>(w2, w2s, out);
}